// round 16
// baseline (speedup 1.0000x reference)
#include <cuda_runtime.h>
#include <cuda_fp16.h>
#include <cstdint>

#define NTHR   1024
#define HEADS  64
#define TOPKN  512
#define SCALE_F 0.041666666666666664f
#define NEGINF __int_as_float(0xff800000)

#define N2 4718592   // uint2 count: 32768*576*2B/8 == 512*64*576*2B/8

__device__ __align__(16) uint2 g_kh[N2];   // kv fp16
__device__ __align__(16) uint2 g_q[N2];    // q fp16

// ---- smem byte offsets ----
#define OFF_IDX   0                       // 512*4
#define OFF_M     2048
#define OFF_L     2304
#define OFF_C     2560
#define OFF_WMAX  2816                    // 8*64*4 -> 4864
#define OFF_WSUM  4864                    // 8*64*4 -> 6912
#define OFF_P     6912                    // P fp16: 64 rows * 272B -> 24320
#define KH_(s)    (24320 + (s)*18432)     // K slice 128x144B fp16; 3 stages -> 79616
#define QH_(s)    (79616 + (s)*9216)      // Q slice 64x144B fp16; 3 stages -> 107264
#define VH_(i)    (24320 + (i)*18432)     // V tile 16x1040B fp16 (16640B) on K stage i, 3 bufs
#define SMEM_TOTAL 107264

__device__ __forceinline__ uint32_t smem_u32(const void* p) {
    uint32_t a;
    asm("{ .reg .u64 t; cvta.to.shared.u64 t, %1; cvt.u32.u64 %0, t; }" : "=r"(a) : "l"(p));
    return a;
}
__device__ __forceinline__ void ldsm4(uint32_t* r, uint32_t a) {
    asm volatile("ldmatrix.sync.aligned.m8n8.x4.shared.b16 {%0,%1,%2,%3}, [%4];"
                 : "=r"(r[0]), "=r"(r[1]), "=r"(r[2]), "=r"(r[3]) : "r"(a));
}
__device__ __forceinline__ void ldsm4t(uint32_t* r, uint32_t a) {
    asm volatile("ldmatrix.sync.aligned.m8n8.x4.trans.shared.b16 {%0,%1,%2,%3}, [%4];"
                 : "=r"(r[0]), "=r"(r[1]), "=r"(r[2]), "=r"(r[3]) : "r"(a));
}
__device__ __forceinline__ void mma16f(float* d, const uint32_t* a, uint32_t b0, uint32_t b1) {
    asm volatile(
        "mma.sync.aligned.m16n8k16.row.col.f32.f16.f16.f32 "
        "{%0,%1,%2,%3}, {%4,%5,%6,%7}, {%8,%9}, {%0,%1,%2,%3};"
        : "+f"(d[0]), "+f"(d[1]), "+f"(d[2]), "+f"(d[3])
        : "r"(a[0]), "r"(a[1]), "r"(a[2]), "r"(a[3]), "r"(b0), "r"(b1));
}
__device__ __forceinline__ void cpa(uint32_t dst, const void* src, uint32_t sz) {
    asm volatile("cp.async.cg.shared.global [%0], [%1], 16, %2;"
                 :: "r"(dst), "l"(src), "r"(sz) : "memory");
}
#define CP_COMMIT() asm volatile("cp.async.commit_group;" ::: "memory")
#define CP_WAIT(n)  asm volatile("cp.async.wait_group %0;" :: "n"(n) : "memory")

__device__ __forceinline__ uint32_t packh2(float x, float y) {
    uint32_t r;
    asm("cvt.rn.f16x2.f32 %0, %1, %2;" : "=r"(r) : "f"(y), "f"(x));  // x -> low half
    return r;
}

// ================= preprocessing: fp32 -> fp16 =================
__global__ __launch_bounds__(256)
void conv_kernel(const float* __restrict__ kv, const float* __restrict__ qq)
{
    uint32_t i = blockIdx.x * 256u + threadIdx.x;
    if (i < N2) {
        float4 v = *reinterpret_cast<const float4*>(kv + (size_t)i * 4);
        g_kh[i] = make_uint2(packh2(v.x, v.y), packh2(v.z, v.w));
    } else {
        uint32_t o = i - N2;
        float4 v = *reinterpret_cast<const float4*>(qq + (size_t)o * 4);
        g_q[o] = make_uint2(packh2(v.x, v.y), packh2(v.z, v.w));
    }
}

// ================= gather issue helpers (1024 threads) =================
__device__ __forceinline__ void issue_kq(uint32_t smb, const int* idx_s,
                                         int ci, int ds, int t, int tid)
{
    const int st = ds % 3;
    {   // K slice [128 keys x 64 d] fp16: 8 threads/row, 16B each
        int row = tid >> 3, sub = tid & 7;
        int gi = idx_s[ci * 128 + row];
        uint32_t sz = gi >= 0 ? 16u : 0u;
        if (gi < 0) gi = 0;
        size_t rb = (size_t)gi * 1152 + (size_t)ds * 128 + sub * 16;
        cpa(smb + KH_(st) + row * 144 + sub * 16, (const char*)g_kh + rb, sz);
    }
    if (tid < 512) {   // Q slice [64 heads x 64 d] fp16, 3-stage
        int row = tid >> 3, sub = tid & 7;
        size_t rb = ((size_t)t * 64 + row) * 1152 + (size_t)ds * 128 + sub * 16;
        cpa(smb + QH_(st) + row * 144 + sub * 16, (const char*)g_q + rb, 16);
    }
}
__device__ __forceinline__ void issue_v(uint32_t smb, const int* idx_s,
                                        int ci, int kst, int tid)
{
    // V tile [16 keys x 512 dv] fp16: 64 threads/row, 16B each; buffer kst%3
    int row = tid >> 6, sub = tid & 63;
    int gi = idx_s[ci * 128 + kst * 16 + row];
    uint32_t sz = gi >= 0 ? 16u : 0u;
    if (gi < 0) gi = 0;
    size_t rb = (size_t)gi * 1152 + sub * 16;
    cpa(smb + VH_(kst % 3) + row * 1040 + sub * 16, (const char*)g_kh + rb, sz);
}

// ================= main attention kernel =================
__global__ __launch_bounds__(NTHR, 1)
void mla_mma_kernel(const int* __restrict__ topk,
                    const float* __restrict__ sink,
                    float* __restrict__ out)
{
    extern __shared__ char sm[];
    const uint32_t smb = smem_u32(sm);
    const int tid = threadIdx.x;
    const int w = tid >> 5, l = tid & 31;
    const int hg = w >> 3;          // 4 head groups of 16
    const int kg = w & 7;           // QK: 16-key group; PV: 64-dv group
    const int t = blockIdx.x;

    int*   idx_s  = reinterpret_cast<int*>(sm + OFF_IDX);
    float* m_s    = reinterpret_cast<float*>(sm + OFF_M);
    float* l_s    = reinterpret_cast<float*>(sm + OFF_L);
    float* c_s    = reinterpret_cast<float*>(sm + OFF_C);
    float* wmax_s = reinterpret_cast<float*>(sm + OFF_WMAX);
    float* wsum_s = reinterpret_cast<float*>(sm + OFF_WSUM);

    if (tid < 512) idx_s[tid] = __ldg(topk + (size_t)t * TOPKN + tid);
    if (tid < HEADS) { m_s[tid] = __ldg(sink + tid); l_s[tid] = 1.f; }
    __syncthreads();

    float o[8][4];
    #pragma unroll
    for (int i = 0; i < 8; ++i)
        #pragma unroll
        for (int j = 0; j < 4; ++j) o[i][j] = 0.f;

    issue_kq(smb, idx_s, 0, 0, t, tid); CP_COMMIT();
    issue_kq(smb, idx_s, 0, 1, t, tid); CP_COMMIT();

    for (int ci = 0; ci < 4; ++ci) {
        float sacc[2][4];
        #pragma unroll
        for (int i = 0; i < 2; ++i)
            #pragma unroll
            for (int j = 0; j < 4; ++j) sacc[i][j] = 0.f;

        // ===== QK: 9 d-slices of 64, 3-stage pipeline =====
        for (int ds = 0; ds < 9; ++ds) {
            if (ds < 8) CP_WAIT(1); else CP_WAIT(0);
            __syncthreads();   // data(ds) visible + all warps done with stage (ds-1)%3
            if (ds < 7) {
                issue_kq(smb, idx_s, ci, ds + 2, t, tid); CP_COMMIT();
            } else if (ds == 7) {
                // stage0's last K reader was ds6, drained by this sync -> V0 can land there
                issue_v(smb, idx_s, ci, 0, tid); CP_COMMIT();
            } else {
                // stage1's last K reader was ds7, drained by this sync -> V1
                issue_v(smb, idx_s, ci, 1, tid); CP_COMMIT();
            }
            const int st = ds % 3;
            #pragma unroll
            for (int ks = 0; ks < 4; ++ks) {
                uint32_t qf[4], kh[4];
                uint32_t qa = smb + QH_(st) + (hg * 16 + (l & 15)) * 144 + (ks * 16 + (l >> 4) * 8) * 2;
                ldsm4(qf, qa);
                uint32_t ka = smb + KH_(st) + (kg * 16 + (l & 15)) * 144 + (ks * 16 + (l >> 4) * 8) * 2;
                ldsm4(kh, ka);
                mma16f(sacc[0], qf, kh[0], kh[2]);
                mma16f(sacc[1], qf, kh[1], kh[3]);
            }
        }

        // ===== chunked online softmax =====
        float rm0 = NEGINF, rm1 = NEGINF;
        #pragma unroll
        for (int nt = 0; nt < 2; ++nt) {
            int kb = ci * 128 + kg * 16 + nt * 8 + (l & 3) * 2;
            bool v0 = idx_s[kb] >= 0, v1 = idx_s[kb + 1] >= 0;
            float a0 = v0 ? sacc[nt][0] * SCALE_F : NEGINF;
            float a1 = v1 ? sacc[nt][1] * SCALE_F : NEGINF;
            float a2 = v0 ? sacc[nt][2] * SCALE_F : NEGINF;
            float a3 = v1 ? sacc[nt][3] * SCALE_F : NEGINF;
            sacc[nt][0] = a0; sacc[nt][1] = a1; sacc[nt][2] = a2; sacc[nt][3] = a3;
            rm0 = fmaxf(rm0, fmaxf(a0, a1));
            rm1 = fmaxf(rm1, fmaxf(a2, a3));
        }
        rm0 = fmaxf(rm0, __shfl_xor_sync(0xffffffffu, rm0, 1));
        rm0 = fmaxf(rm0, __shfl_xor_sync(0xffffffffu, rm0, 2));
        rm1 = fmaxf(rm1, __shfl_xor_sync(0xffffffffu, rm1, 1));
        rm1 = fmaxf(rm1, __shfl_xor_sync(0xffffffffu, rm1, 2));
        if ((l & 3) == 0) {
            wmax_s[kg * 64 + hg * 16 + (l >> 2)]     = rm0;
            wmax_s[kg * 64 + hg * 16 + 8 + (l >> 2)] = rm1;
        }
        __syncthreads();
        if (tid < HEADS) {
            float mo = m_s[tid];
            float mn = mo;
            #pragma unroll
            for (int g = 0; g < 8; ++g) mn = fmaxf(mn, wmax_s[g * 64 + tid]);
            float cr = __expf(mo - mn);
            m_s[tid] = mn; c_s[tid] = cr; l_s[tid] *= cr;
        }
        __syncthreads();
        float mr0 = m_s[hg * 16 + (l >> 2)];
        float mr1 = m_s[hg * 16 + 8 + (l >> 2)];
        float sum0 = 0.f, sum1 = 0.f;
        #pragma unroll
        for (int nt = 0; nt < 2; ++nt) {
            float e0 = __expf(sacc[nt][0] - mr0);
            float e1 = __expf(sacc[nt][1] - mr0);
            float e2 = __expf(sacc[nt][2] - mr1);
            float e3 = __expf(sacc[nt][3] - mr1);
            sum0 += e0 + e1; sum1 += e2 + e3;
            uint32_t col = (uint32_t)(kg * 16 + nt * 8 + (l & 3) * 2) * 2;
            uint32_t r0o = (uint32_t)(hg * 16 + (l >> 2)) * 272 + col;
            *reinterpret_cast<uint32_t*>(sm + OFF_P + r0o)           = packh2(e0, e1);
            *reinterpret_cast<uint32_t*>(sm + OFF_P + r0o + 8 * 272) = packh2(e2, e3);
        }
        sum0 += __shfl_xor_sync(0xffffffffu, sum0, 1);
        sum0 += __shfl_xor_sync(0xffffffffu, sum0, 2);
        sum1 += __shfl_xor_sync(0xffffffffu, sum1, 1);
        sum1 += __shfl_xor_sync(0xffffffffu, sum1, 2);
        if ((l & 3) == 0) {
            wsum_s[kg * 64 + hg * 16 + (l >> 2)]     = sum0;
            wsum_s[kg * 64 + hg * 16 + 8 + (l >> 2)] = sum1;
        }
        __syncthreads();
        if (tid < HEADS) {
            float acc = 0.f;
            #pragma unroll
            for (int g = 0; g < 8; ++g) acc += wsum_s[g * 64 + tid];
            l_s[tid] += acc;
        }
        float c0 = c_s[hg * 16 + (l >> 2)];
        float c1 = c_s[hg * 16 + 8 + (l >> 2)];
        #pragma unroll
        for (int nt = 0; nt < 8; ++nt) {
            o[nt][0] *= c0; o[nt][1] *= c0; o[nt][2] *= c1; o[nt][3] *= c1;
        }

        // ===== PV: 8 V tiles of 16 keys, 3 buffers, ONE sync per iteration =====
        for (int kst = 0; kst < 8; ++kst) {
            if (kst < 7) CP_WAIT(1); else CP_WAIT(0);
            __syncthreads();   // V(kst) visible; buf (kst-1)%3 fully read; P visible (kst==0)
            uint32_t ph[4];
            uint32_t pa = smb + OFF_P + (hg * 16 + (l & 15)) * 272 +
                          (kst * 16 + (l >> 4) * 8) * 2;
            ldsm4(ph, pa);
            #pragma unroll
            for (int dvt = 0; dvt < 4; ++dvt) {
                uint32_t vh[4];
                uint32_t va = smb + VH_(kst % 3) + (l & 15) * 1040 +
                              (kg * 64 + dvt * 16 + (l >> 4) * 8) * 2;
                ldsm4t(vh, va);
                mma16f(o[dvt * 2],     ph, vh[0], vh[1]);
                mma16f(o[dvt * 2 + 1], ph, vh[2], vh[3]);
            }
            // writer targets buf (kst+2)%3 == (kst-1)%3, drained by THIS iteration's sync
            if (kst < 6) {
                issue_v(smb, idx_s, ci, kst + 2, tid); CP_COMMIT();
            } else if (kst == 7 && ci < 3) {
                // stage0 region (V buf0): last read kst6, drained by kst7's sync
                issue_kq(smb, idx_s, ci + 1, 0, t, tid); CP_COMMIT();
            }
        }
        __syncthreads();   // buf1/stage1 (kst7's V buf was 7%3=1) fully read
        if (ci < 3) {
            issue_kq(smb, idx_s, ci + 1, 1, t, tid); CP_COMMIT();
        }
    }

    // ============ epilogue: normalize + store ============
    float n0 = 1.f / l_s[hg * 16 + (l >> 2)];
    float n1 = 1.f / l_s[hg * 16 + 8 + (l >> 2)];
    float* ob0 = out + ((size_t)t * HEADS + hg * 16 + (l >> 2)) * 512;
    float* ob1 = ob0 + 8 * 512;
    #pragma unroll
    for (int nt = 0; nt < 8; ++nt) {
        int dv = kg * 64 + nt * 8 + (l & 3) * 2;
        *reinterpret_cast<float2*>(ob0 + dv) = make_float2(o[nt][0] * n0, o[nt][1] * n0);
        *reinterpret_cast<float2*>(ob1 + dv) = make_float2(o[nt][2] * n1, o[nt][3] * n1);
    }
}

extern "C" void kernel_launch(void* const* d_in, const int* in_sizes, int n_in,
                              void* d_out, int out_size)
{
    const float* q    = (const float*)d_in[0];
    const float* kv   = (const float*)d_in[1];
    const int*   topk = (const int*)d_in[2];
    const float* sink = (const float*)d_in[3];
    float* out = (float*)d_out;

    conv_kernel<<<(2 * N2) / 256, 256>>>(kv, q);

    cudaFuncSetAttribute(mla_mma_kernel, cudaFuncAttributeMaxDynamicSharedMemorySize, SMEM_TOTAL);
    mla_mma_kernel<<<512, NTHR, SMEM_TOTAL>>>(topk, sink, out);
}

// round 17
// speedup vs baseline: 1.3320x; 1.3320x over previous
#include <cuda_runtime.h>
#include <cuda_fp16.h>
#include <cstdint>

#define NTHR   1024
#define HEADS  64
#define TOPKN  512
#define SCALE_F 0.041666666666666664f
#define NEGINF __int_as_float(0xff800000)

#define N2 4718592   // uint2 count: 32768*576*2B/8

__device__ __align__(16) uint2 g_kh[N2];   // kv fp16

// ---- smem byte offsets ----
#define OFF_IDX   0                       // 512*4
#define OFF_M     2048
#define OFF_L     2304
#define OFF_C     2560
#define OFF_WMAX  2816                    // 8*64*4 -> 4864
#define OFF_WSUM  4864                    // 8*64*4 -> 6912
#define OFF_P     6912                    // P fp16: 64 rows * 272B -> 24320
#define KH_(s)    (24320 + (s)*18432)     // K slice 128x144B fp16; 3 stages -> 79616
#define VH_(i)    (24320 + (i)*18432)     // V tile 16x1040B fp16 (16640B) on K stage i
#define QP_(d)    (79616 + (d)*9216)      // persistent Q: 9 slices x (64 rows x 144B) -> 162560
#define SMEM_TOTAL 162560

__device__ __forceinline__ uint32_t smem_u32(const void* p) {
    uint32_t a;
    asm("{ .reg .u64 t; cvta.to.shared.u64 t, %1; cvt.u32.u64 %0, t; }" : "=r"(a) : "l"(p));
    return a;
}
__device__ __forceinline__ void ldsm4(uint32_t* r, uint32_t a) {
    asm volatile("ldmatrix.sync.aligned.m8n8.x4.shared.b16 {%0,%1,%2,%3}, [%4];"
                 : "=r"(r[0]), "=r"(r[1]), "=r"(r[2]), "=r"(r[3]) : "r"(a));
}
__device__ __forceinline__ void ldsm4t(uint32_t* r, uint32_t a) {
    asm volatile("ldmatrix.sync.aligned.m8n8.x4.trans.shared.b16 {%0,%1,%2,%3}, [%4];"
                 : "=r"(r[0]), "=r"(r[1]), "=r"(r[2]), "=r"(r[3]) : "r"(a));
}
__device__ __forceinline__ void mma16f(float* d, const uint32_t* a, uint32_t b0, uint32_t b1) {
    asm volatile(
        "mma.sync.aligned.m16n8k16.row.col.f32.f16.f16.f32 "
        "{%0,%1,%2,%3}, {%4,%5,%6,%7}, {%8,%9}, {%0,%1,%2,%3};"
        : "+f"(d[0]), "+f"(d[1]), "+f"(d[2]), "+f"(d[3])
        : "r"(a[0]), "r"(a[1]), "r"(a[2]), "r"(a[3]), "r"(b0), "r"(b1));
}
__device__ __forceinline__ void cpa(uint32_t dst, const void* src, uint32_t sz) {
    asm volatile("cp.async.cg.shared.global [%0], [%1], 16, %2;"
                 :: "r"(dst), "l"(src), "r"(sz) : "memory");
}
#define CP_COMMIT() asm volatile("cp.async.commit_group;" ::: "memory")
#define CP_WAIT(n)  asm volatile("cp.async.wait_group %0;" :: "n"(n) : "memory")

__device__ __forceinline__ uint32_t packh2(float x, float y) {
    uint32_t r;
    asm("cvt.rn.f16x2.f32 %0, %1, %2;" : "=r"(r) : "f"(y), "f"(x));  // x -> low half
    return r;
}

// ================= preprocessing: kv fp32 -> fp16 =================
__global__ __launch_bounds__(256)
void conv_kernel(const float* __restrict__ kv)
{
    uint32_t i = blockIdx.x * 256u + threadIdx.x;
    float4 v = *reinterpret_cast<const float4*>(kv + (size_t)i * 4);
    g_kh[i] = make_uint2(packh2(v.x, v.y), packh2(v.z, v.w));
}

// ================= gather issue helpers (1024 threads) =================
__device__ __forceinline__ void issue_k(uint32_t smb, const int* idx_s,
                                        int ci, int ds, int tid)
{
    // K slice [128 keys x 64 d] fp16: 8 threads/row, 16B each
    const int st = ds % 3;
    int row = tid >> 3, sub = tid & 7;
    int gi = idx_s[ci * 128 + row];
    uint32_t sz = gi >= 0 ? 16u : 0u;
    if (gi < 0) gi = 0;
    size_t rb = (size_t)gi * 1152 + (size_t)ds * 128 + sub * 16;
    cpa(smb + KH_(st) + row * 144 + sub * 16, (const char*)g_kh + rb, sz);
}
__device__ __forceinline__ void issue_v(uint32_t smb, const int* idx_s,
                                        int ci, int kst, int tid)
{
    // V tile [16 keys x 512 dv] fp16: 64 threads/row, 16B each
    int row = tid >> 6, sub = tid & 63;
    int gi = idx_s[ci * 128 + kst * 16 + row];
    uint32_t sz = gi >= 0 ? 16u : 0u;
    if (gi < 0) gi = 0;
    size_t rb = (size_t)gi * 1152 + sub * 16;
    cpa(smb + VH_(kst & 1) + row * 1040 + sub * 16, (const char*)g_kh + rb, sz);
}

// ================= main attention kernel =================
__global__ __launch_bounds__(NTHR, 1)
void mla_mma_kernel(const float* __restrict__ q,
                    const int* __restrict__ topk,
                    const float* __restrict__ sink,
                    float* __restrict__ out)
{
    extern __shared__ char sm[];
    const uint32_t smb = smem_u32(sm);
    const int tid = threadIdx.x;
    const int w = tid >> 5, l = tid & 31;
    const int hg = w >> 3;          // 4 head groups of 16
    const int kg = w & 7;           // QK: 16-key group; PV: 64-dv group
    const int t = blockIdx.x;

    int*   idx_s  = reinterpret_cast<int*>(sm + OFF_IDX);
    float* m_s    = reinterpret_cast<float*>(sm + OFF_M);
    float* l_s    = reinterpret_cast<float*>(sm + OFF_L);
    float* c_s    = reinterpret_cast<float*>(sm + OFF_C);
    float* wmax_s = reinterpret_cast<float*>(sm + OFF_WMAX);
    float* wsum_s = reinterpret_cast<float*>(sm + OFF_WSUM);

    if (tid < 512) idx_s[tid] = __ldg(topk + (size_t)t * TOPKN + tid);
    if (tid < HEADS) { m_s[tid] = __ldg(sink + tid); l_s[tid] = 1.f; }

    // ---- load + convert this token's Q (64x576 fp32) into persistent smem fp16 ----
    {
        const float4* qsrc = reinterpret_cast<const float4*>(q + (size_t)t * HEADS * 576);
        #pragma unroll
        for (int p = 0; p < 9; ++p) {                 // 9216 float4s / 1024 threads
            int i = p * NTHR + tid;
            float4 v = __ldg(qsrc + i);
            int row = i / 144;                        // 144 float4s per row
            int col = (i % 144) * 4;
            int ds = col >> 6, c64 = col & 63;
            uint32_t off = QP_(ds) + (uint32_t)row * 144 + (uint32_t)c64 * 2;
            *reinterpret_cast<uint32_t*>(sm + off)     = packh2(v.x, v.y);
            *reinterpret_cast<uint32_t*>(sm + off + 4) = packh2(v.z, v.w);
        }
    }
    __syncthreads();   // idx_s + Q visible

    float o[8][4];
    #pragma unroll
    for (int i = 0; i < 8; ++i)
        #pragma unroll
        for (int j = 0; j < 4; ++j) o[i][j] = 0.f;

    issue_k(smb, idx_s, 0, 0, tid); CP_COMMIT();
    issue_k(smb, idx_s, 0, 1, tid); CP_COMMIT();

    for (int ci = 0; ci < 4; ++ci) {
        float sacc[2][4];
        #pragma unroll
        for (int i = 0; i < 2; ++i)
            #pragma unroll
            for (int j = 0; j < 4; ++j) sacc[i][j] = 0.f;

        // ===== QK: 9 d-slices of 64, 3-stage pipeline =====
        for (int ds = 0; ds < 9; ++ds) {
            if (ds < 8) CP_WAIT(1); else CP_WAIT(0);
            __syncthreads();   // data(ds) visible + all warps done with stage (ds-1)%3
            if (ds < 7) {
                issue_k(smb, idx_s, ci, ds + 2, tid); CP_COMMIT();
            } else if (ds == 8) {
                // K stages 0/1 free -> prefetch first two V tiles onto them
                issue_v(smb, idx_s, ci, 0, tid); CP_COMMIT();
                issue_v(smb, idx_s, ci, 1, tid); CP_COMMIT();
            }
            const int st = ds % 3;
            #pragma unroll
            for (int ks = 0; ks < 4; ++ks) {
                uint32_t qf[4], kh[4];
                uint32_t qa = smb + QP_(ds) + (hg * 16 + (l & 15)) * 144 + (ks * 16 + (l >> 4) * 8) * 2;
                ldsm4(qf, qa);
                uint32_t ka = smb + KH_(st) + (kg * 16 + (l & 15)) * 144 + (ks * 16 + (l >> 4) * 8) * 2;
                ldsm4(kh, ka);
                mma16f(sacc[0], qf, kh[0], kh[2]);
                mma16f(sacc[1], qf, kh[1], kh[3]);
            }
        }

        // ===== chunked online softmax =====
        float rm0 = NEGINF, rm1 = NEGINF;
        #pragma unroll
        for (int nt = 0; nt < 2; ++nt) {
            int kb = ci * 128 + kg * 16 + nt * 8 + (l & 3) * 2;
            bool v0 = idx_s[kb] >= 0, v1 = idx_s[kb + 1] >= 0;
            float a0 = v0 ? sacc[nt][0] * SCALE_F : NEGINF;
            float a1 = v1 ? sacc[nt][1] * SCALE_F : NEGINF;
            float a2 = v0 ? sacc[nt][2] * SCALE_F : NEGINF;
            float a3 = v1 ? sacc[nt][3] * SCALE_F : NEGINF;
            sacc[nt][0] = a0; sacc[nt][1] = a1; sacc[nt][2] = a2; sacc[nt][3] = a3;
            rm0 = fmaxf(rm0, fmaxf(a0, a1));
            rm1 = fmaxf(rm1, fmaxf(a2, a3));
        }
        rm0 = fmaxf(rm0, __shfl_xor_sync(0xffffffffu, rm0, 1));
        rm0 = fmaxf(rm0, __shfl_xor_sync(0xffffffffu, rm0, 2));
        rm1 = fmaxf(rm1, __shfl_xor_sync(0xffffffffu, rm1, 1));
        rm1 = fmaxf(rm1, __shfl_xor_sync(0xffffffffu, rm1, 2));
        if ((l & 3) == 0) {
            wmax_s[kg * 64 + hg * 16 + (l >> 2)]     = rm0;
            wmax_s[kg * 64 + hg * 16 + 8 + (l >> 2)] = rm1;
        }
        __syncthreads();
        if (tid < HEADS) {
            float mo = m_s[tid];
            float mn = mo;
            #pragma unroll
            for (int g = 0; g < 8; ++g) mn = fmaxf(mn, wmax_s[g * 64 + tid]);
            float cr = __expf(mo - mn);
            m_s[tid] = mn; c_s[tid] = cr; l_s[tid] *= cr;
        }
        __syncthreads();
        float mr0 = m_s[hg * 16 + (l >> 2)];
        float mr1 = m_s[hg * 16 + 8 + (l >> 2)];
        float sum0 = 0.f, sum1 = 0.f;
        #pragma unroll
        for (int nt = 0; nt < 2; ++nt) {
            float e0 = __expf(sacc[nt][0] - mr0);
            float e1 = __expf(sacc[nt][1] - mr0);
            float e2 = __expf(sacc[nt][2] - mr1);
            float e3 = __expf(sacc[nt][3] - mr1);
            sum0 += e0 + e1; sum1 += e2 + e3;
            uint32_t col = (uint32_t)(kg * 16 + nt * 8 + (l & 3) * 2) * 2;
            uint32_t r0o = (uint32_t)(hg * 16 + (l >> 2)) * 272 + col;
            *reinterpret_cast<uint32_t*>(sm + OFF_P + r0o)           = packh2(e0, e1);
            *reinterpret_cast<uint32_t*>(sm + OFF_P + r0o + 8 * 272) = packh2(e2, e3);
        }
        sum0 += __shfl_xor_sync(0xffffffffu, sum0, 1);
        sum0 += __shfl_xor_sync(0xffffffffu, sum0, 2);
        sum1 += __shfl_xor_sync(0xffffffffu, sum1, 1);
        sum1 += __shfl_xor_sync(0xffffffffu, sum1, 2);
        if ((l & 3) == 0) {
            wsum_s[kg * 64 + hg * 16 + (l >> 2)]     = sum0;
            wsum_s[kg * 64 + hg * 16 + 8 + (l >> 2)] = sum1;
        }
        __syncthreads();
        if (tid < HEADS) {
            float acc = 0.f;
            #pragma unroll
            for (int g = 0; g < 8; ++g) acc += wsum_s[g * 64 + tid];
            l_s[tid] += acc;
        }
        float c0 = c_s[hg * 16 + (l >> 2)];
        float c1 = c_s[hg * 16 + 8 + (l >> 2)];
        #pragma unroll
        for (int nt = 0; nt < 8; ++nt) {
            o[nt][0] *= c0; o[nt][1] *= c0; o[nt][2] *= c1; o[nt][3] *= c1;
        }

        // ===== PV: 8 V tiles of 16 keys, double-buffered =====
        for (int kst = 0; kst < 8; ++kst) {
            if (kst < 7 || ci < 3) CP_WAIT(1); else CP_WAIT(0);
            __syncthreads();   // V data visible (cross-warp) + P visible (kst==0)
            uint32_t ph[4];
            uint32_t pa = smb + OFF_P + (hg * 16 + (l & 15)) * 272 +
                          (kst * 16 + (l >> 4) * 8) * 2;
            ldsm4(ph, pa);
            #pragma unroll
            for (int dvt = 0; dvt < 4; ++dvt) {
                uint32_t vh[4];
                uint32_t va = smb + VH_(kst & 1) + (l & 15) * 1040 +
                              (kg * 64 + dvt * 16 + (l >> 4) * 8) * 2;
                ldsm4t(vh, va);
                mma16f(o[dvt * 2],     ph, vh[0], vh[1]);
                mma16f(o[dvt * 2 + 1], ph, vh[2], vh[3]);
            }
            __syncthreads();   // buffer kst&1 free (all warps done)
            if (kst < 6) {
                issue_v(smb, idx_s, ci, kst + 2, tid); CP_COMMIT();
            } else if (kst == 6 && ci < 3) {
                issue_k(smb, idx_s, ci + 1, 0, tid); CP_COMMIT();  // into stage0 (== V buf0)
            } else if (kst == 7 && ci < 3) {
                issue_k(smb, idx_s, ci + 1, 1, tid); CP_COMMIT();  // into stage1 (== V buf1)
            }
        }
    }

    // ============ epilogue: normalize + store ============
    float n0 = 1.f / l_s[hg * 16 + (l >> 2)];
    float n1 = 1.f / l_s[hg * 16 + 8 + (l >> 2)];
    float* ob0 = out + ((size_t)t * HEADS + hg * 16 + (l >> 2)) * 512;
    float* ob1 = ob0 + 8 * 512;
    #pragma unroll
    for (int nt = 0; nt < 8; ++nt) {
        int dv = kg * 64 + nt * 8 + (l & 3) * 2;
        *reinterpret_cast<float2*>(ob0 + dv) = make_float2(o[nt][0] * n0, o[nt][1] * n0);
        *reinterpret_cast<float2*>(ob1 + dv) = make_float2(o[nt][2] * n1, o[nt][3] * n1);
    }
}

extern "C" void kernel_launch(void* const* d_in, const int* in_sizes, int n_in,
                              void* d_out, int out_size)
{
    const float* q    = (const float*)d_in[0];
    const float* kv   = (const float*)d_in[1];
    const int*   topk = (const int*)d_in[2];
    const float* sink = (const float*)d_in[3];
    float* out = (float*)d_out;

    conv_kernel<<<N2 / 256, 256>>>(kv);

    cudaFuncSetAttribute(mla_mma_kernel, cudaFuncAttributeMaxDynamicSharedMemorySize, SMEM_TOTAL);
    mla_mma_kernel<<<512, NTHR, SMEM_TOTAL>>>(q, topk, sink, out);
}